// round 2
// baseline (speedup 1.0000x reference)
#include <cuda_runtime.h>
#include <math.h>

#define BSZ 128
#define NN 2000
#define DD 256
#define HH 8
#define HDIM 32
#define CTX 64
#define CN 8

#define MCHUNKS 16
#define MROWS (NN / MCHUNKS)      // 125

#define NSPLIT 8
#define WPB 8                      // warps per block in attention kernel
#define NPART (NSPLIT * WPB)       // 64 partials per batch
#define CHUNK (NN / NSPLIT)        // 250

// ---------------- scratch (static device globals; no allocation) ----------------
__device__ float g_pm[BSZ * MCHUNKS * DD];                 // partial sums for mean
__device__ float g_qproj[BSZ * HH * DD];                   // Wk_h^T Qh
__device__ float g_qnk[BSZ * HH * CN];                     // Wn_k,h^T Qh
__device__ float g_ml[BSZ * NPART * HH * 2];               // per-partial (m, l)
__device__ float g_accE[(size_t)BSZ * NPART * HH * DD];    // per-partial sum p*enc
__device__ float g_accNF[BSZ * NPART * HH * CN];           // per-partial sum p*nf
__device__ float g_qlog[BSZ * DD];                         // Wk2^T glimpse
__device__ float g_qlogn[BSZ * CN];                        // Wn_l^T glimpse
__device__ int   g_maskmode;                               // 0=uint8, 1=int32, 2=float32

// ---------------- K0: detect mask dtype (bytes of first 256000 are always valid) ----------------
__global__ void k_maskdetect(const unsigned char* __restrict__ m) {
    __shared__ int sBig, sOff;
    if (threadIdx.x == 0) { sBig = 0; sOff = 0; }
    __syncthreads();
    int big = 0, off = 0;
    const int total = BSZ * NN;   // element count == minimum byte count (uint8 case)
    for (int i = threadIdx.x; i < total; i += blockDim.x) {
        unsigned char v = m[i];
        if (v > 1) big = 1;
        else if (v == 1 && (i & 3)) off = 1;
    }
    if (big) atomicOr(&sBig, 1);
    if (off) atomicOr(&sOff, 1);
    __syncthreads();
    if (threadIdx.x == 0)
        g_maskmode = sBig ? 2 : (sOff ? 0 : 1);
}

// ---------------- K1: partial sums over n for mean ----------------
__global__ void k_mean_partial(const float* __restrict__ enc) {
    int s = blockIdx.x, b = blockIdx.y, tid = threadIdx.x;
    const float* p = enc + ((size_t)(b * NN + s * MROWS)) * DD + tid;
    float acc = 0.f;
#pragma unroll 5
    for (int j = 0; j < MROWS; j++) acc += p[(size_t)j * DD];
    g_pm[(b * MCHUNKS + s) * DD + tid] = acc;
}

// ---------------- K2: per-batch query construction + projections ----------------
__global__ void k_setup(const float* __restrict__ shelf,
                        const float* __restrict__ ctx,
                        const float* __restrict__ Wk,
                        const float* __restrict__ Wq,
                        const float* __restrict__ Wc,
                        const float* __restrict__ Wg,
                        const float* __restrict__ Wn,
                        const int* __restrict__ curnode) {
    __shared__ float sMean[DD], sCur[DD], sCn[DD], sCtx[CTX], sQ[DD];
    int b = blockIdx.x, tid = threadIdx.x;

    float m = 0.f;
#pragma unroll
    for (int s = 0; s < MCHUNKS; s++) m += g_pm[(b * MCHUNKS + s) * DD + tid];
    sMean[tid] = m * (1.0f / NN);

    int cn = curnode[b];
    sCur[tid] = shelf[((size_t)b * NN + cn) * DD + tid];
    if (tid < CTX) sCtx[tid] = ctx[b * CTX + tid];
    __syncthreads();

    float cx = 0.f;
#pragma unroll
    for (int c = 0; c < CTX; c++) cx += Wc[tid * CTX + c] * sCtx[c];
    sCn[tid] = cx;
    __syncthreads();

    float q = 0.f;
    for (int e = 0; e < DD; e++) q += Wq[tid * 2 * DD + e] * sCur[e];
    for (int e = 0; e < DD; e++) q += Wq[tid * 2 * DD + DD + e] * sCn[e];
    for (int e = 0; e < DD; e++) q += Wg[tid * DD + e] * sMean[e];   // + graph_embed
    sQ[tid] = q;
    __syncthreads();

    // qproj[h][tid] = sum_i Q[h*32+i] * Wk[h*32+i][tid]   (coalesced over tid)
#pragma unroll
    for (int h = 0; h < HH; h++) {
        float a = 0.f;
#pragma unroll
        for (int i = 0; i < HDIM; i++) a += sQ[h * HDIM + i] * Wk[(h * HDIM + i) * DD + tid];
        g_qproj[(b * HH + h) * DD + tid] = a;
    }
    if (tid < HH * CN) {
        int h = tid >> 3, c = tid & 7;
        float a = 0.f;
#pragma unroll
        for (int i = 0; i < HDIM; i++) a += sQ[h * HDIM + i] * Wn[(h * HDIM + i) * CN + c];
        g_qnk[b * HH * CN + tid] = a;
    }
}

// ---------------- K3: flash attention pass (compat + online softmax + accV) ----------------
__global__ void __launch_bounds__(256) k_attn(const float* __restrict__ enc,
                                              const float* __restrict__ nfeat) {
    __shared__ float sQp[HH * DD];
    __shared__ float sQn[HH * CN];
    int s = blockIdx.x, b = blockIdx.y;
    int tid = threadIdx.x, w = tid >> 5, lane = tid & 31;

    for (int i = tid; i < HH * DD; i += 256) sQp[i] = g_qproj[b * HH * DD + i];
    if (tid < HH * CN) sQn[tid] = g_qnk[b * HH * CN + tid];
    __syncthreads();

    float m[HH], l[HH], aE[HH][8];
    float a0 = 0.f, a1 = 0.f;     // accNF: lane holds flat idx (lane) and (lane+32)
#pragma unroll
    for (int h = 0; h < HH; h++) {
        m[h] = -INFINITY; l[h] = 0.f;
#pragma unroll
        for (int k = 0; k < 8; k++) aE[h][k] = 0.f;
    }
    const int h0 = lane >> 3, c0 = lane & 7;
    const float SC = 0.1767766952966369f;  // 1/sqrt(32)

    int nend = s * CHUNK + CHUNK;
    for (int n = s * CHUNK + w; n < nend; n += WPB) {
        const float* er = enc + ((size_t)(b * NN) + n) * DD;
        float e[8];
#pragma unroll
        for (int k = 0; k < 8; k++) e[k] = er[32 * k + lane];
        float nfq = nfeat[((size_t)(b * NN) + n) * CN + c0];

        float c[HH];
#pragma unroll
        for (int h = 0; h < HH; h++) {
            float a = 0.f;
#pragma unroll
            for (int k = 0; k < 8; k++) a += e[k] * sQp[h * DD + 32 * k + lane];
            if (lane < CN) a += sQn[h * CN + lane] * nfq;   // distributed nf-term
            c[h] = a;
        }
#pragma unroll
        for (int h = 0; h < HH; h++) {
#pragma unroll
            for (int o = 16; o > 0; o >>= 1) c[h] += __shfl_xor_sync(0xffffffffu, c[h], o);
        }
#pragma unroll
        for (int h = 0; h < HH; h++) {
            float cc = c[h] * SC;
            if (cc > m[h]) {                       // warp-uniform branch, rare
                float al = __expf(m[h] - cc);      // exp(-inf)=0 on first hit
                m[h] = cc; l[h] *= al;
#pragma unroll
                for (int k = 0; k < 8; k++) aE[h][k] *= al;
                if (h == h0)     a0 *= al;
                if (h == h0 + 4) a1 *= al;
            }
            float p = __expf(cc - m[h]);
            l[h] += p;
#pragma unroll
            for (int k = 0; k < 8; k++) aE[h][k] += p * e[k];
            if (h == h0)     a0 += p * nfq;
            if (h == h0 + 4) a1 += p * nfq;
        }
    }

    int part = s * WPB + w;
    size_t base = ((size_t)(b * NPART) + part) * HH;
#pragma unroll
    for (int h = 0; h < HH; h++) {
#pragma unroll
        for (int k = 0; k < 8; k++)
            g_accE[(base + h) * DD + 32 * k + lane] = aE[h][k];
    }
    g_accNF[base * CN + lane] = a0;
    g_accNF[base * CN + 32 + lane] = a1;
    if (lane == 0) {
#pragma unroll
        for (int h = 0; h < HH; h++) {
            g_ml[(base + h) * 2 + 0] = m[h];
            g_ml[(base + h) * 2 + 1] = l[h];
        }
    }
}

// ---------------- K4: combine partials + epilogue (heads -> glimpse -> qlog) ----------------
__global__ void k_combine(const float* __restrict__ Wv,
                          const float* __restrict__ Wout,
                          const float* __restrict__ Wk2,
                          const float* __restrict__ Wn) {
    __shared__ float sScale[NPART * HH];
    __shared__ float sLinv[HH];
    __shared__ float sMst[HH];
    __shared__ float sV[HH * DD];
    __shared__ float sNF[HH * CN];
    __shared__ float sO[DD];
    __shared__ float sG[DD];
    int b = blockIdx.x, tid = threadIdx.x;

    if (tid < HH) {
        float mm = -INFINITY;
        for (int p = 0; p < NPART; p++)
            mm = fmaxf(mm, g_ml[((b * NPART + p) * HH + tid) * 2]);
        sMst[tid] = mm;
    }
    __syncthreads();
    for (int i = tid; i < NPART * HH; i += 256) {
        int p = i / HH, h = i % HH;
        float mm = g_ml[((b * NPART + p) * HH + h) * 2];
        sScale[p * HH + h] = __expf(mm - sMst[h]);
    }
    __syncthreads();
    if (tid < HH) {
        float L = 0.f;
        for (int p = 0; p < NPART; p++)
            L += g_ml[((b * NPART + p) * HH + tid) * 2 + 1] * sScale[p * HH + tid];
        sLinv[tid] = 1.0f / L;
    }
    __syncthreads();

    // combined, normalized weighted-enc per head
#pragma unroll
    for (int h = 0; h < HH; h++) {
        float a = 0.f;
        for (int p = 0; p < NPART; p++)
            a += g_accE[(((size_t)(b * NPART) + p) * HH + h) * DD + tid] * sScale[p * HH + h];
        sV[h * DD + tid] = a * sLinv[h];
    }
    if (tid < HH * CN) {
        int h = tid >> 3;
        float a = 0.f;
        for (int p = 0; p < NPART; p++)
            a += g_accNF[(b * NPART + p) * (HH * CN) + tid] * sScale[p * HH + h];
        sNF[tid] = a * sLinv[h];
    }
    __syncthreads();

    // heads output: o[h*32+i] = Wv row (h*32+i) . vbar[h] + Wn v-part row . nfbar[h]
    {
        int h = tid >> 5;
        float a = 0.f;
        for (int e = 0; e < DD; e++) a += Wv[tid * DD + e] * sV[h * DD + e];
#pragma unroll
        for (int c = 0; c < CN; c++) a += Wn[(DD + tid) * CN + c] * sNF[h * CN + c];
        sO[tid] = a;
    }
    __syncthreads();
    {
        float g = 0.f;
        for (int e = 0; e < DD; e++) g += Wout[tid * DD + e] * sO[e];
        sG[tid] = g;
    }
    __syncthreads();
    {
        float q = 0.f;
        for (int d = 0; d < DD; d++) q += sG[d] * Wk2[d * DD + tid];   // coalesced
        g_qlog[b * DD + tid] = q;
    }
    if (tid < CN) {
        float q = 0.f;
        for (int d = 0; d < DD; d++) q += sG[d] * Wn[(2 * DD + d) * CN + tid];
        g_qlogn[b * CN + tid] = q;
    }
}

// ---------------- K5: logits + masked softmax ----------------
__global__ void __launch_bounds__(256) k_logits(const float* __restrict__ enc,
                                                const float* __restrict__ nfeat,
                                                const unsigned char* __restrict__ mask,
                                                float* __restrict__ out) {
    __shared__ float sQl[DD];
    __shared__ float sQn[CN];
    __shared__ float sLog[NN];
    __shared__ float sRed[40];
    int b = blockIdx.x, tid = threadIdx.x, w = tid >> 5, lane = tid & 31;
    int mode = g_maskmode;

    sQl[tid] = g_qlog[b * DD + tid];
    if (tid < CN) sQn[tid] = g_qlogn[b * CN + tid];
    __syncthreads();

    for (int n = w; n < NN; n += 8) {
        const float* er = enc + ((size_t)(b * NN) + n) * DD;
        float a = 0.f;
#pragma unroll
        for (int k = 0; k < 8; k++) a += er[32 * k + lane] * sQl[32 * k + lane];
        if (lane < CN) a += nfeat[((size_t)(b * NN) + n) * CN + lane] * sQn[lane];
#pragma unroll
        for (int o = 16; o > 0; o >>= 1) a += __shfl_xor_sync(0xffffffffu, a, o);
        if (lane == 0) {
            size_t idx = (size_t)b * NN + n;
            bool mk;
            if (mode == 2)      mk = ((const float*)mask)[idx] != 0.0f;
            else if (mode == 1) mk = ((const int*)mask)[idx] != 0;
            else                mk = mask[idx] != 0;
            float lg = tanhf(a * (1.0f / 16.0f)) * 10.0f;
            sLog[n] = mk ? -INFINITY : lg;
        }
    }
    __syncthreads();

    // block max
    float mx = -INFINITY;
    for (int n = tid; n < NN; n += 256) mx = fmaxf(mx, sLog[n]);
#pragma unroll
    for (int o = 16; o > 0; o >>= 1) mx = fmaxf(mx, __shfl_xor_sync(0xffffffffu, mx, o));
    if (lane == 0) sRed[w] = mx;
    __syncthreads();
    if (tid == 0) {
        float m2 = -INFINITY;
        for (int i = 0; i < 8; i++) m2 = fmaxf(m2, sRed[i]);
        sRed[32] = m2;
    }
    __syncthreads();
    float M = sRed[32];

    float sm = 0.f;
    for (int n = tid; n < NN; n += 256) sm += __expf(sLog[n] - M);
#pragma unroll
    for (int o = 16; o > 0; o >>= 1) sm += __shfl_xor_sync(0xffffffffu, sm, o);
    if (lane == 0) sRed[8 + w] = sm;
    __syncthreads();
    if (tid == 0) {
        float s2 = 0.f;
        for (int i = 0; i < 8; i++) s2 += sRed[8 + i];
        sRed[33] = 1.0f / s2;
    }
    __syncthreads();
    float inv = sRed[33];
    for (int n = tid; n < NN; n += 256)
        out[(size_t)b * NN + n] = __expf(sLog[n] - M) * inv;
}

// ---------------- launch ----------------
extern "C" void kernel_launch(void* const* d_in, const int* in_sizes, int n_in,
                              void* d_out, int out_size) {
    const float* shelf = (const float*)d_in[0];
    const float* enc   = (const float*)d_in[1];
    const float* ctx   = (const float*)d_in[2];
    const float* nfeat = (const float*)d_in[3];
    const float* Wk    = (const float*)d_in[4];
    const float* Wv    = (const float*)d_in[5];
    const float* Wk2   = (const float*)d_in[6];
    const float* Wq    = (const float*)d_in[7];
    const float* Wout  = (const float*)d_in[8];
    const float* Wc    = (const float*)d_in[9];
    const float* Wg    = (const float*)d_in[10];
    const float* Wn    = (const float*)d_in[11];
    const int*   cur   = (const int*)d_in[12];
    const unsigned char* mask = (const unsigned char*)d_in[13];
    float* out = (float*)d_out;

    k_maskdetect<<<1, 256>>>(mask);
    k_mean_partial<<<dim3(MCHUNKS, BSZ), 256>>>(enc);
    k_setup<<<BSZ, 256>>>(shelf, ctx, Wk, Wq, Wc, Wg, Wn, cur);
    k_attn<<<dim3(NSPLIT, BSZ), 256>>>(enc, nfeat);
    k_combine<<<BSZ, 256>>>(Wv, Wout, Wk2, Wn);
    k_logits<<<BSZ, 256>>>(enc, nfeat, mask, out);
}

// round 4
// speedup vs baseline: 2.0456x; 2.0456x over previous
#include <cuda_runtime.h>
#include <math.h>

#define BSZ 128
#define NN 2000
#define DD 256
#define HH 8
#define CN 8
#define CTX 64

#define MCHUNKS 16
#define MROWS 125

#define NSPLIT 8
#define CHUNK 250
#define PAD 260
#define PAD4 65

// ---------------- scratch ----------------
__device__ float g_pm[BSZ * MCHUNKS * DD];
__device__ float g_qproj[BSZ * HH * DD];
__device__ float g_qnk[BSZ * HH * CN];
__device__ float g_ml[BSZ * NSPLIT * HH * 2];
__device__ float g_accE[BSZ * NSPLIT * HH * DD];
__device__ float g_accNF[BSZ * NSPLIT * HH * CN];
__device__ float g_qlog[BSZ * DD];
__device__ float g_qlogn[BSZ * CN];
__device__ float g_logits[BSZ * NN];
__device__ int   g_flags[2];   // [0]=big byte seen, [1]=off-aligned 1 seen

// ---------------- K-1: zero detection flags ----------------
__global__ void k_zero() { g_flags[0] = 0; g_flags[1] = 0; }

// ---------------- K0: detect mask dtype (parallel) ----------------
__global__ void k_maskdetect(const unsigned char* __restrict__ m) {
    int big = 0, off = 0;
    int base = blockIdx.x * 4000;
    for (int i = base + threadIdx.x; i < base + 4000; i += 256) {
        unsigned char v = m[i];
        if (v > 1) big = 1;
        else if (v == 1 && (i & 3)) off = 1;
    }
    if (__syncthreads_or(big)) { if (threadIdx.x == 0) atomicOr(&g_flags[0], 1); }
    if (__syncthreads_or(off)) { if (threadIdx.x == 0) atomicOr(&g_flags[1], 1); }
}

// ---------------- K1: partial sums over n for mean ----------------
__global__ void k_mean_partial(const float* __restrict__ enc) {
    int s = blockIdx.x, b = blockIdx.y, tid = threadIdx.x;
    const float* p = enc + ((size_t)(b * NN + s * MROWS)) * DD + tid;
    float acc = 0.f;
#pragma unroll 8
    for (int j = 0; j < MROWS; j++) acc += p[(size_t)j * DD];
    g_pm[(b * MCHUNKS + s) * DD + tid] = acc;
}

// ---------------- K2: per-batch query construction + projections ----------------
__global__ void k_setup(const float* __restrict__ shelf,
                        const float* __restrict__ ctx,
                        const float* __restrict__ Wk,
                        const float* __restrict__ Wq,
                        const float* __restrict__ Wc,
                        const float* __restrict__ Wg,
                        const float* __restrict__ Wn,
                        const int* __restrict__ curnode) {
    __shared__ float sMean[DD], sCur[DD], sCn[DD], sCtx[CTX], sQ[DD];
    int b = blockIdx.x, tid = threadIdx.x;

    float m = 0.f;
#pragma unroll
    for (int s = 0; s < MCHUNKS; s++) m += g_pm[(b * MCHUNKS + s) * DD + tid];
    sMean[tid] = m * (1.0f / NN);

    int cn = curnode[b];
    sCur[tid] = shelf[((size_t)b * NN + cn) * DD + tid];
    if (tid < CTX) sCtx[tid] = ctx[b * CTX + tid];
    __syncthreads();

    float cx = 0.f;
#pragma unroll
    for (int c = 0; c < CTX; c++) cx += Wc[tid * CTX + c] * sCtx[c];
    sCn[tid] = cx;
    __syncthreads();

    float q = 0.f;
#pragma unroll 8
    for (int e = 0; e < DD; e++) q += Wq[tid * 2 * DD + e] * sCur[e];
#pragma unroll 8
    for (int e = 0; e < DD; e++) q += Wq[tid * 2 * DD + DD + e] * sCn[e];
#pragma unroll 8
    for (int e = 0; e < DD; e++) q += Wg[tid * DD + e] * sMean[e];
    sQ[tid] = q;
    __syncthreads();

#pragma unroll
    for (int h = 0; h < HH; h++) {
        float a = 0.f;
#pragma unroll
        for (int i = 0; i < 32; i++) a += sQ[h * 32 + i] * Wk[(h * 32 + i) * DD + tid];
        g_qproj[(b * HH + h) * DD + tid] = a;
    }
    if (tid < HH * CN) {
        int h = tid >> 3, c = tid & 7;
        float a = 0.f;
#pragma unroll
        for (int i = 0; i < 32; i++) a += sQ[h * 32 + i] * Wn[(h * 32 + i) * CN + c];
        g_qnk[b * HH * CN + tid] = a;
    }
}

// ---------------- K3: tiled flash attention, block-level online softmax ----------------
__global__ void __launch_bounds__(256) k_attn(const float* __restrict__ enc,
                                              const float* __restrict__ nfeat) {
    __shared__ float sQ[HH * PAD];      // qproj, padded rows
    __shared__ float sQn[HH * 9];       // qnk, padded
    __shared__ float sE[32 * PAD];      // enc tile
    __shared__ float sNF[32 * CN];      // nf tile
    __shared__ float sC[32 * HH];       // compat / p
    __shared__ float sMW[8 * HH];       // per-warp tile-max partials
    __shared__ float sM[HH];            // running max
    __shared__ float sAl[HH];           // per-tile rescale
    __shared__ float sLr[256];          // l reduction

    const int s = blockIdx.x, b = blockIdx.y;
    const int t = threadIdx.x, lane = t & 31, w = t >> 5;
    const int iA = t >> 3, hA = t & 7;      // phase-A role
    const int hB = t >> 3, cB = t & 7;      // accNF role (t<64)

    for (int idx = t; idx < HH * DD; idx += 256)
        sQ[(idx >> 8) * PAD + (idx & 255)] = g_qproj[b * HH * DD + idx];
    if (t < HH * CN) sQn[(t >> 3) * 9 + (t & 7)] = g_qnk[b * HH * CN + t];
    if (t < HH) sM[t] = -INFINITY;

    float aE[HH];
#pragma unroll
    for (int h = 0; h < HH; h++) aE[h] = 0.f;
    float lrun = 0.f, aNF = 0.f;

    const float SC = 0.1767766952966369f;   // 1/sqrt(32)
    const size_t rowbase = (size_t)(b * NN + s * CHUNK);

    for (int k = 0; k < 8; k++) {
        const int n0 = k * 32;
        const int T = (k == 7) ? (CHUNK - 224) : 32;   // 26 on last tile
        __syncthreads();   // protect sE/sC from previous tile's readers

        // stage enc tile (coalesced float4, conflict-free STS)
        const float4* gsrc = (const float4*)(enc + (rowbase + n0) * DD);
        const int nf4 = T * 64;
#pragma unroll
        for (int r = 0; r < 8; r++) {
            int idx = r * 256 + t;
            if (idx < nf4) {
                float4 v = gsrc[idx];
                int n = idx >> 6, e = (idx & 63) << 2;
                *(float4*)(sE + n * PAD + e) = v;
            }
        }
        if (t < T * 2) {
            float4 v = ((const float4*)(nfeat + (rowbase + n0) * CN))[t];
            *(float4*)(&sNF[t * 4]) = v;
        }
        __syncthreads();

        // ---- phase A: compat[i][h] ----
        float c = 0.f;
        {
            const float4* eR = (const float4*)sE + iA * PAD4;
            const float4* qR = (const float4*)sQ + hA * PAD4;
#pragma unroll 8
            for (int e4 = 0; e4 < 64; e4++) {
                float4 ev = eR[e4], qv = qR[e4];
                c += ev.x * qv.x; c += ev.y * qv.y;
                c += ev.z * qv.z; c += ev.w * qv.w;
            }
#pragma unroll
            for (int cc = 0; cc < CN; cc++)
                c += sQn[hA * 9 + cc] * sNF[iA * CN + cc];
            c *= SC;
        }
        float cm = (iA < T) ? c : -INFINITY;
        cm = fmaxf(cm, __shfl_xor_sync(0xffffffffu, cm, 8));
        cm = fmaxf(cm, __shfl_xor_sync(0xffffffffu, cm, 16));
        if (lane < 8) sMW[w * 8 + lane] = cm;
        __syncthreads();
        if (t < HH) {
            float mt = sMW[t];
#pragma unroll
            for (int ww = 1; ww < 8; ww++) mt = fmaxf(mt, sMW[ww * 8 + t]);
            float mold = sM[t];
            float mnew = fmaxf(mold, mt);
            sAl[t] = __expf(mold - mnew);
            sM[t] = mnew;
        }
        __syncthreads();
        {
            float alpha_h = sAl[hA];
            if (iA < T) {
                float p = __expf(c - sM[hA]);
                sC[iA * HH + hA] = p;
                lrun = lrun * alpha_h + p;
            } else {
                lrun *= alpha_h;
            }
        }
        __syncthreads();

        // ---- phase B: accumulate aE (thread = column e = t) ----
#pragma unroll
        for (int h = 0; h < HH; h++) aE[h] *= sAl[h];
        {
            const float* eCol = sE + t;
#pragma unroll 8
            for (int n = 0; n < T; n++) {
                float4 p0 = *(const float4*)(sC + n * HH);
                float4 p1 = *(const float4*)(sC + n * HH + 4);
                float ev = eCol[n * PAD];
                aE[0] += p0.x * ev; aE[1] += p0.y * ev;
                aE[2] += p0.z * ev; aE[3] += p0.w * ev;
                aE[4] += p1.x * ev; aE[5] += p1.y * ev;
                aE[6] += p1.z * ev; aE[7] += p1.w * ev;
            }
        }
        if (t < 64) {
            aNF *= sAl[hB];
            for (int n = 0; n < T; n++)
                aNF += sC[n * HH + hB] * sNF[n * CN + cB];
        }
    }

    __syncthreads();
    sLr[t] = lrun;
    __syncthreads();
    const int part = b * NSPLIT + s;
#pragma unroll
    for (int h = 0; h < HH; h++)
        g_accE[((size_t)part * HH + h) * DD + t] = aE[h];
    if (t < 64) g_accNF[part * 64 + t] = aNF;
    if (t < HH) {
        float L = 0.f;
#pragma unroll
        for (int i = 0; i < 32; i++) L += sLr[i * 8 + t];
        g_ml[(part * HH + t) * 2 + 0] = sM[t];
        g_ml[(part * HH + t) * 2 + 1] = L;
    }
}

// ---------------- K4: combine partials + epilogue ----------------
__global__ void k_combine(const float* __restrict__ Wv,
                          const float* __restrict__ Wout,
                          const float* __restrict__ Wk2,
                          const float* __restrict__ Wn) {
    __shared__ float sScale[NSPLIT * HH];
    __shared__ float sLinv[HH];
    __shared__ float sMst[HH];
    __shared__ float sV[HH * DD];
    __shared__ float sNFc[HH * CN];
    __shared__ float sO[DD];
    __shared__ float sG[DD];
    int b = blockIdx.x, tid = threadIdx.x;

    if (tid < HH) {
        float mm = -INFINITY;
#pragma unroll
        for (int p = 0; p < NSPLIT; p++)
            mm = fmaxf(mm, g_ml[((b * NSPLIT + p) * HH + tid) * 2]);
        sMst[tid] = mm;
    }
    __syncthreads();
    if (tid < NSPLIT * HH) {
        int p = tid >> 3, h = tid & 7;
        float mm = g_ml[((b * NSPLIT + p) * HH + h) * 2];
        sScale[p * HH + h] = __expf(mm - sMst[h]);
    }
    __syncthreads();
    if (tid < HH) {
        float L = 0.f;
#pragma unroll
        for (int p = 0; p < NSPLIT; p++)
            L += g_ml[((b * NSPLIT + p) * HH + tid) * 2 + 1] * sScale[p * HH + tid];
        sLinv[tid] = 1.0f / L;
    }
    __syncthreads();

#pragma unroll
    for (int h = 0; h < HH; h++) {
        float a = 0.f;
#pragma unroll
        for (int p = 0; p < NSPLIT; p++)
            a += g_accE[(((size_t)(b * NSPLIT) + p) * HH + h) * DD + tid] * sScale[p * HH + h];
        sV[h * DD + tid] = a * sLinv[h];
    }
    if (tid < HH * CN) {
        int h = tid >> 3;
        float a = 0.f;
#pragma unroll
        for (int p = 0; p < NSPLIT; p++)
            a += g_accNF[(b * NSPLIT + p) * (HH * CN) + tid] * sScale[p * HH + h];
        sNFc[tid] = a * sLinv[h];
    }
    __syncthreads();

    {
        int h = tid >> 5;
        float a = 0.f;
#pragma unroll 8
        for (int e = 0; e < DD; e++) a += Wv[tid * DD + e] * sV[h * DD + e];
#pragma unroll
        for (int c = 0; c < CN; c++) a += Wn[(DD + tid) * CN + c] * sNFc[h * CN + c];
        sO[tid] = a;
    }
    __syncthreads();
    {
        float g = 0.f;
#pragma unroll 8
        for (int e = 0; e < DD; e++) g += Wout[tid * DD + e] * sO[e];
        sG[tid] = g;
    }
    __syncthreads();
    {
        float q = 0.f;
#pragma unroll 8
        for (int d = 0; d < DD; d++) q += sG[d] * Wk2[d * DD + tid];
        g_qlog[b * DD + tid] = q;
    }
    if (tid < CN) {
        float q = 0.f;
#pragma unroll 8
        for (int d = 0; d < DD; d++) q += sG[d] * Wn[(2 * DD + d) * CN + tid];
        g_qlogn[b * CN + tid] = q;
    }
}

// ---------------- K5a: masked logits over a chunk ----------------
__global__ void __launch_bounds__(256) k_logits_part(const float* __restrict__ enc,
                                                     const float* __restrict__ nfeat,
                                                     const unsigned char* __restrict__ mask) {
    __shared__ float sQl[DD];
    __shared__ float sQn2[CN];
    int s = blockIdx.x, b = blockIdx.y;
    int t = threadIdx.x, w = t >> 5, lane = t & 31;
    int mode = g_flags[0] ? 2 : (g_flags[1] ? 0 : 1);

    sQl[t] = g_qlog[b * DD + t];
    if (t < CN) sQn2[t] = g_qlogn[b * CN + t];
    __syncthreads();

    int nend = s * CHUNK + CHUNK;
    for (int n = s * CHUNK + w; n < nend; n += 8) {
        const float* er = enc + ((size_t)(b * NN) + n) * DD;
        float a = 0.f;
#pragma unroll
        for (int k = 0; k < 8; k++) a += er[32 * k + lane] * sQl[32 * k + lane];
        if (lane < CN) a += nfeat[((size_t)(b * NN) + n) * CN + lane] * sQn2[lane];
#pragma unroll
        for (int o = 16; o > 0; o >>= 1) a += __shfl_xor_sync(0xffffffffu, a, o);
        if (lane == 0) {
            size_t idx = (size_t)b * NN + n;
            bool mk;
            if (mode == 2)      mk = ((const float*)mask)[idx] != 0.0f;
            else if (mode == 1) mk = ((const int*)mask)[idx] != 0;
            else                mk = mask[idx] != 0;
            float lg = tanhf(a * (1.0f / 16.0f)) * 10.0f;
            g_logits[idx] = mk ? -INFINITY : lg;
        }
    }
}

// ---------------- K5b: per-batch softmax ----------------
__global__ void __launch_bounds__(256) k_softmax(float* __restrict__ out) {
    __shared__ float sL[NN];
    __shared__ float sRed[40];
    int b = blockIdx.x, t = threadIdx.x, w = t >> 5, lane = t & 31;

    const float4* src = (const float4*)(g_logits + (size_t)b * NN);
    for (int i = t; i < NN / 4; i += 256) {
        float4 v = src[i];
        *(float4*)(sL + i * 4) = v;
    }
    __syncthreads();

    float mx = -INFINITY;
    for (int n = t; n < NN; n += 256) mx = fmaxf(mx, sL[n]);
#pragma unroll
    for (int o = 16; o > 0; o >>= 1) mx = fmaxf(mx, __shfl_xor_sync(0xffffffffu, mx, o));
    if (lane == 0) sRed[w] = mx;
    __syncthreads();
    if (t == 0) {
        float m2 = -INFINITY;
#pragma unroll
        for (int i = 0; i < 8; i++) m2 = fmaxf(m2, sRed[i]);
        sRed[32] = m2;
    }
    __syncthreads();
    float M = sRed[32];

    float sm = 0.f;
    for (int n = t; n < NN; n += 256) sm += __expf(sL[n] - M);
#pragma unroll
    for (int o = 16; o > 0; o >>= 1) sm += __shfl_xor_sync(0xffffffffu, sm, o);
    if (lane == 0) sRed[8 + w] = sm;
    __syncthreads();
    if (t == 0) {
        float s2 = 0.f;
#pragma unroll
        for (int i = 0; i < 8; i++) s2 += sRed[8 + i];
        sRed[33] = 1.0f / s2;
    }
    __syncthreads();
    float inv = sRed[33];
    for (int n = t; n < NN; n += 256)
        out[(size_t)b * NN + n] = __expf(sL[n] - M) * inv;
}

// ---------------- launch ----------------
extern "C" void kernel_launch(void* const* d_in, const int* in_sizes, int n_in,
                              void* d_out, int out_size) {
    const float* shelf = (const float*)d_in[0];
    const float* enc   = (const float*)d_in[1];
    const float* ctx   = (const float*)d_in[2];
    const float* nfeat = (const float*)d_in[3];
    const float* Wk    = (const float*)d_in[4];
    const float* Wv    = (const float*)d_in[5];
    const float* Wk2   = (const float*)d_in[6];
    const float* Wq    = (const float*)d_in[7];
    const float* Wout  = (const float*)d_in[8];
    const float* Wc    = (const float*)d_in[9];
    const float* Wg    = (const float*)d_in[10];
    const float* Wn    = (const float*)d_in[11];
    const int*   cur   = (const int*)d_in[12];
    const unsigned char* mask = (const unsigned char*)d_in[13];
    float* out = (float*)d_out;

    k_zero<<<1, 1>>>();
    k_maskdetect<<<64, 256>>>(mask);
    k_mean_partial<<<dim3(MCHUNKS, BSZ), 256>>>(enc);
    k_setup<<<BSZ, 256>>>(shelf, ctx, Wk, Wq, Wc, Wg, Wn, cur);
    k_attn<<<dim3(NSPLIT, BSZ), 256>>>(enc, nfeat);
    k_combine<<<BSZ, 256>>>(Wv, Wout, Wk2, Wn);
    k_logits_part<<<dim3(NSPLIT, BSZ), 256>>>(enc, nfeat, mask);
    k_softmax<<<BSZ, 256>>>(out);
}